// round 3
// baseline (speedup 1.0000x reference)
#include <cuda_runtime.h>

// GraphSAGE 2-layer encoder.
//   deg[i]   = #incoming edges; inv = 1/max(deg,1)
//   layer(h) = inv * segsum(h[src], dst) @ Wl + b + h @ Wr
// restructured as y = h@Wl ; z = h@Wr + b ; out[i] = inv[i]*sum_{j in N(i)} y[j] + z[i]

#define NMAX 100000
#define EMAX 1600000
#define F 64

__device__ __align__(16) float g_y[NMAX * F];
__device__ __align__(16) float g_z[NMAX * F];
__device__ __align__(16) float g_h[NMAX * F];
__device__ float g_invdeg[NMAX];
__device__ int   g_cnt[NMAX];
__device__ int   g_cursor[NMAX];
__device__ int   g_rowptr[NMAX + 1];
__device__ int   g_col[EMAX];
__device__ int   g_part[256];

// ---------------------------------------------------------------- CSR build
__global__ void k_init(int n) {
    int i = blockIdx.x * blockDim.x + threadIdx.x;
    if (i < n) { g_cnt[i] = 0; g_cursor[i] = 0; }
}

__global__ void k_hist(const int* __restrict__ dst, int E) {
    int e = blockIdx.x * blockDim.x + threadIdx.x;
    if (e < E) atomicAdd(&g_cnt[dst[e]], 1);
}

// pass 1: per-1024-chunk exclusive scan; emit chunk totals
__global__ void k_scan1(int n) {
    __shared__ int sh[1024];
    int tid = threadIdx.x;
    int i = blockIdx.x * 1024 + tid;
    int v = (i < n) ? g_cnt[i] : 0;
    sh[tid] = v;
    __syncthreads();
    #pragma unroll
    for (int off = 1; off < 1024; off <<= 1) {
        int t = (tid >= off) ? sh[tid - off] : 0;
        __syncthreads();
        sh[tid] += t;
        __syncthreads();
    }
    if (i < n) {
        g_rowptr[i] = sh[tid] - v;               // exclusive
        g_invdeg[i] = 1.0f / (float)max(v, 1);
    }
    if (tid == 1023) g_part[blockIdx.x] = sh[1023];
}

// pass 2: scan the (<=128) chunk totals
__global__ void k_scan2(int nb) {
    __shared__ int sh[128];
    int tid = threadIdx.x;
    int v = (tid < nb) ? g_part[tid] : 0;
    sh[tid] = v;
    __syncthreads();
    #pragma unroll
    for (int off = 1; off < 128; off <<= 1) {
        int t = (tid >= off) ? sh[tid - off] : 0;
        __syncthreads();
        sh[tid] += t;
        __syncthreads();
    }
    if (tid < nb) g_part[tid] = sh[tid] - v;     // exclusive
}

// pass 3: add chunk offsets
__global__ void k_scan3(int n, int E) {
    int i = blockIdx.x * blockDim.x + threadIdx.x;
    if (i < n) g_rowptr[i] += g_part[i >> 10];
    if (i == 0) g_rowptr[n] = E;
}

__global__ void k_scatter(const int* __restrict__ src, const int* __restrict__ dst, int E) {
    int e = blockIdx.x * blockDim.x + threadIdx.x;
    if (e < E) {
        int d = dst[e];
        int p = g_rowptr[d] + atomicAdd(&g_cursor[d], 1);
        g_col[p] = src[e];
    }
}

// --------------------------------------------------- fused dual GEMM (y & z)
// y = X @ Wl ; z = X @ Wr + b.   64-row tile per block, 256 threads,
// each thread computes a 4x4 tile for BOTH outputs (32 FMA per k-step).
__global__ __launch_bounds__(256) void k_gemm(const float* __restrict__ Xext,
                                              const float* __restrict__ Wl,
                                              const float* __restrict__ Wr,
                                              const float* __restrict__ B,
                                              int use_h, int n) {
    __shared__ float xs[64 * 68];   // padded stride to dodge bank conflicts
    __shared__ float wls[64 * 64];
    __shared__ float wrs[64 * 64];
    __shared__ float bs[64];

    const float* X = use_h ? (const float*)g_h : Xext;
    int tid  = threadIdx.x;
    int row0 = blockIdx.x * 64;

    for (int t = tid; t < 1024; t += 256) {
        ((float4*)wls)[t] = ((const float4*)Wl)[t];
        ((float4*)wrs)[t] = ((const float4*)Wr)[t];
    }
    if (tid < 64) bs[tid] = B[tid];
    for (int t = tid; t < 1024; t += 256) {
        int r = t >> 4, c4 = (t & 15) << 2;
        int g = row0 + r;
        float4 v = make_float4(0.f, 0.f, 0.f, 0.f);
        if (g < n) v = *(const float4*)&X[g * 64 + c4];
        xs[r * 68 + c4 + 0] = v.x;
        xs[r * 68 + c4 + 1] = v.y;
        xs[r * 68 + c4 + 2] = v.z;
        xs[r * 68 + c4 + 3] = v.w;
    }
    __syncthreads();

    int tx = tid & 15, ty = tid >> 4;
    int c = tx << 2, r = ty << 2;

    float4 ay[4], az[4];
    #pragma unroll
    for (int i = 0; i < 4; i++) {
        ay[i] = make_float4(0.f, 0.f, 0.f, 0.f);
        az[i] = make_float4(0.f, 0.f, 0.f, 0.f);
    }

    #pragma unroll 4
    for (int k = 0; k < 64; ++k) {
        float4 wl4 = *(const float4*)&wls[k * 64 + c];
        float4 wr4 = *(const float4*)&wrs[k * 64 + c];
        #pragma unroll
        for (int i = 0; i < 4; i++) {
            float xv = xs[(r + i) * 68 + k];
            ay[i].x += xv * wl4.x; ay[i].y += xv * wl4.y;
            ay[i].z += xv * wl4.z; ay[i].w += xv * wl4.w;
            az[i].x += xv * wr4.x; az[i].y += xv * wr4.y;
            az[i].z += xv * wr4.z; az[i].w += xv * wr4.w;
        }
    }

    float4 bb = make_float4(bs[c], bs[c + 1], bs[c + 2], bs[c + 3]);
    #pragma unroll
    for (int i = 0; i < 4; i++) {
        int g = row0 + r + i;
        if (g < n) {
            *(float4*)&g_y[g * 64 + c] = ay[i];
            float4 zz = az[i];
            zz.x += bb.x; zz.y += bb.y; zz.z += bb.z; zz.w += bb.w;
            *(float4*)&g_z[g * 64 + c] = zz;
        }
    }
}

// --------------------------------------------------------- gather-aggregate
// out[i] = maybe_relu( inv[i] * sum_{e in row i} y[col[e]] + z[i] )
// 64 threads per node (one per feature dim); edge loop unrolled x4 for MLP.
__global__ __launch_bounds__(256) void k_agg(float* __restrict__ Oext,
                                             int do_relu, int n) {
    int node = (blockIdx.x << 2) + (threadIdx.x >> 6);
    int d    = threadIdx.x & 63;
    if (node >= n) return;
    float* O = Oext ? Oext : (float*)g_h;

    int s = g_rowptr[node], e = g_rowptr[node + 1];
    float a0 = 0.f, a1 = 0.f, a2 = 0.f, a3 = 0.f;
    int i = s;
    for (; i + 3 < e; i += 4) {
        int j0 = g_col[i], j1 = g_col[i + 1], j2 = g_col[i + 2], j3 = g_col[i + 3];
        a0 += g_y[j0 * 64 + d];
        a1 += g_y[j1 * 64 + d];
        a2 += g_y[j2 * 64 + d];
        a3 += g_y[j3 * 64 + d];
    }
    for (; i < e; ++i) a0 += g_y[g_col[i] * 64 + d];

    float v = (a0 + a1 + a2 + a3) * g_invdeg[node] + g_z[node * 64 + d];
    if (do_relu) v = fmaxf(v, 0.f);
    O[node * 64 + d] = v;
}

// ------------------------------------------------------------------- launch
extern "C" void kernel_launch(void* const* d_in, const int* in_sizes, int n_in,
                              void* d_out, int out_size) {
    const float* x   = (const float*)d_in[0];
    const int*   ei  = (const int*)d_in[1];
    const float* w1l = (const float*)d_in[2];
    const float* b1l = (const float*)d_in[3];
    const float* w1r = (const float*)d_in[4];
    const float* w2l = (const float*)d_in[5];
    const float* b2l = (const float*)d_in[6];
    const float* w2r = (const float*)d_in[7];
    float* out = (float*)d_out;

    int n = in_sizes[0] / F;
    int E = in_sizes[1] / 2;
    const int* src = ei;
    const int* dst = ei + E;

    int nb1024 = (n + 1023) / 1024;

    k_init<<<(n + 255) / 256, 256>>>(n);
    k_hist<<<(E + 255) / 256, 256>>>(dst, E);
    k_scan1<<<nb1024, 1024>>>(n);
    k_scan2<<<1, 128>>>(nb1024);
    k_scan3<<<(n + 255) / 256, 256>>>(n, E);
    k_scatter<<<(E + 255) / 256, 256>>>(src, dst, E);

    // layer 1: y = x@w1l, z = x@w1r + b1l; h = relu(agg)
    k_gemm<<<(n + 63) / 64, 256>>>(x, w1l, w1r, b1l, /*use_h=*/0, n);
    k_agg<<<(n + 3) / 4, 256>>>(nullptr, /*relu=*/1, n);

    // layer 2: y = h@w2l, z = h@w2r + b2l; out = agg
    k_gemm<<<(n + 63) / 64, 256>>>(nullptr, w2l, w2r, b2l, /*use_h=*/1, n);
    k_agg<<<(n + 3) / 4, 256>>>(out, /*relu=*/0, n);
}

// round 4
// speedup vs baseline: 1.1486x; 1.1486x over previous
#include <cuda_runtime.h>
#include <cuda_fp16.h>

// GraphSAGE 2-layer encoder, restructured:
//   y = h@Wl (fp16), z = h@Wr + b (fp32), out[i] = inv[i]*sum_{j in N(i)} y[j] + z[i]
// Layer-1 agg + layer-2 GEMM fused (h never hits global memory).

#define NMAX 100000
#define EMAX 1600000
#define F 64

__device__ __align__(16) __half g_ya[NMAX * F];   // layer-1 y (fp16)
__device__ __align__(16) __half g_yb[NMAX * F];   // layer-2 y (fp16)
__device__ __align__(16) float  g_z1[NMAX * F];
__device__ __align__(16) float  g_z2[NMAX * F];
__device__ float g_invdeg[NMAX];
__device__ int   g_cnt[NMAX];        // zero-init at load; re-zeroed by k_agg2 tail
__device__ int   g_rowptr[NMAX + 1];
__device__ int   g_wcur[NMAX];       // working cursor = copy of rowptr
__device__ int   g_col[EMAX];
__device__ int   g_part[128];

// ---------------------------------------------------------------- CSR build
__global__ void k_hist(const int* __restrict__ dst, int E) {
    int e = blockIdx.x * blockDim.x + threadIdx.x;
    if (e < E) atomicAdd(&g_cnt[dst[e]], 1);
}

// pass 1: per-1024-chunk exclusive scan; emit chunk totals; invdeg
__global__ void k_scan1(int n) {
    __shared__ int sh[1024];
    int tid = threadIdx.x;
    int i = blockIdx.x * 1024 + tid;
    int v = (i < n) ? g_cnt[i] : 0;
    sh[tid] = v;
    __syncthreads();
    #pragma unroll
    for (int off = 1; off < 1024; off <<= 1) {
        int t = (tid >= off) ? sh[tid - off] : 0;
        __syncthreads();
        sh[tid] += t;
        __syncthreads();
    }
    if (i < n) {
        g_rowptr[i] = sh[tid] - v;               // chunk-local exclusive
        g_invdeg[i] = 1.0f / (float)max(v, 1);
    }
    if (tid == 1023) g_part[blockIdx.x] = sh[1023];
}

// pass 2+3 fused: every block redundantly scans the chunk totals, then adds
// its offset slice and mirrors rowptr into the working cursor.
__global__ __launch_bounds__(256) void k_scan23(int n, int E, int nb) {
    __shared__ int sh[128], sh2[128];
    int tid = threadIdx.x;
    if (tid < 128) sh[tid] = (tid < nb) ? g_part[tid] : 0;
    __syncthreads();
    int orig = (tid < 128) ? sh[tid] : 0;
    #pragma unroll
    for (int off = 1; off < 128; off <<= 1) {
        int t = 0;
        if (tid < 128 && tid >= off) t = sh[tid - off];
        __syncthreads();
        if (tid < 128) sh[tid] += t;
        __syncthreads();
    }
    if (tid < 128) sh2[tid] = sh[tid] - orig;    // exclusive chunk offsets
    __syncthreads();
    int i = blockIdx.x * blockDim.x + tid;
    if (i < n) {
        int rp = g_rowptr[i] + sh2[i >> 10];
        g_rowptr[i] = rp;
        g_wcur[i]   = rp;
    }
    if (i == 0) g_rowptr[n] = E;
}

__global__ void k_scatter(const int* __restrict__ src, const int* __restrict__ dst, int E) {
    int e = blockIdx.x * blockDim.x + threadIdx.x;
    if (e < E) {
        int p = atomicAdd(&g_wcur[dst[e]], 1);
        g_col[p] = src[e];
    }
}

// --------------------------------------------------- layer-1 dual GEMM
// ya = X @ Wl (fp16) ; z1 = X @ Wr + b (fp32)
__global__ __launch_bounds__(256) void k_gemm1(const float* __restrict__ X,
                                               const float* __restrict__ Wl,
                                               const float* __restrict__ Wr,
                                               const float* __restrict__ B,
                                               int n) {
    __shared__ float xs[64 * 68];
    __shared__ float wls[64 * 64];
    __shared__ float wrs[64 * 64];
    __shared__ float bs[64];

    int tid  = threadIdx.x;
    int row0 = blockIdx.x * 64;

    for (int t = tid; t < 1024; t += 256) {
        ((float4*)wls)[t] = ((const float4*)Wl)[t];
        ((float4*)wrs)[t] = ((const float4*)Wr)[t];
    }
    if (tid < 64) bs[tid] = B[tid];
    for (int t = tid; t < 1024; t += 256) {
        int r = t >> 4, c4 = (t & 15) << 2;
        int g = row0 + r;
        float4 v = make_float4(0.f, 0.f, 0.f, 0.f);
        if (g < n) v = *(const float4*)&X[g * 64 + c4];
        xs[r * 68 + c4 + 0] = v.x; xs[r * 68 + c4 + 1] = v.y;
        xs[r * 68 + c4 + 2] = v.z; xs[r * 68 + c4 + 3] = v.w;
    }
    __syncthreads();

    int tx = tid & 15, ty = tid >> 4;
    int c = tx << 2, r = ty << 2;

    float4 ay[4], az[4];
    #pragma unroll
    for (int i = 0; i < 4; i++) {
        ay[i] = make_float4(0.f, 0.f, 0.f, 0.f);
        az[i] = make_float4(0.f, 0.f, 0.f, 0.f);
    }
    #pragma unroll 4
    for (int k = 0; k < 64; ++k) {
        float4 wl4 = *(const float4*)&wls[k * 64 + c];
        float4 wr4 = *(const float4*)&wrs[k * 64 + c];
        #pragma unroll
        for (int i = 0; i < 4; i++) {
            float xv = xs[(r + i) * 68 + k];
            ay[i].x += xv * wl4.x; ay[i].y += xv * wl4.y;
            ay[i].z += xv * wl4.z; ay[i].w += xv * wl4.w;
            az[i].x += xv * wr4.x; az[i].y += xv * wr4.y;
            az[i].z += xv * wr4.z; az[i].w += xv * wr4.w;
        }
    }

    float4 bb = make_float4(bs[c], bs[c + 1], bs[c + 2], bs[c + 3]);
    #pragma unroll
    for (int i = 0; i < 4; i++) {
        int g = row0 + r + i;
        if (g < n) {
            *(__half2*)&g_ya[g * 64 + c]     = __floats2half2_rn(ay[i].x, ay[i].y);
            *(__half2*)&g_ya[g * 64 + c + 2] = __floats2half2_rn(ay[i].z, ay[i].w);
            float4 zz = az[i];
            zz.x += bb.x; zz.y += bb.y; zz.z += bb.z; zz.w += bb.w;
            *(float4*)&g_z1[g * 64 + c] = zz;
        }
    }
}

// -------------------------------- fused layer-1 aggregate + layer-2 dual GEMM
// phase 1: h[nl] = relu(inv*sum ya[col] + z1) -> smem (64 nodes)
// phase 2: yb = h @ W2l (fp16); z2 = h @ W2r + b2 (fp32)
__global__ __launch_bounds__(256) void k_fused(const float* __restrict__ Wl,
                                               const float* __restrict__ Wr,
                                               const float* __restrict__ B,
                                               int n) {
    __shared__ float xs[64 * 68];
    __shared__ float wls[64 * 64];
    __shared__ float wrs[64 * 64];
    __shared__ float bs[64];

    int tid  = threadIdx.x;
    int row0 = blockIdx.x * 64;
    int lane = tid & 31, w = tid >> 5;

    for (int t = tid; t < 1024; t += 256) {
        ((float4*)wls)[t] = ((const float4*)Wl)[t];
        ((float4*)wrs)[t] = ((const float4*)Wr)[t];
    }
    if (tid < 64) bs[tid] = B[tid];

    // phase 1: warp per node, lane owns dims (2*lane, 2*lane+1)
    const __half2* Y = (const __half2*)g_ya;
    #pragma unroll 1
    for (int pass = 0; pass < 8; ++pass) {
        int nl   = pass * 8 + w;
        int node = row0 + nl;
        if (node < n) {
            int s = g_rowptr[node], e = g_rowptr[node + 1];
            float2 a0 = {0.f,0.f}, a1 = {0.f,0.f}, a2 = {0.f,0.f}, a3 = {0.f,0.f};
            int i = s;
            for (; i + 3 < e; i += 4) {
                int j0 = g_col[i], j1 = g_col[i+1], j2 = g_col[i+2], j3 = g_col[i+3];
                float2 v0 = __half22float2(Y[j0 * 32 + lane]);
                float2 v1 = __half22float2(Y[j1 * 32 + lane]);
                float2 v2 = __half22float2(Y[j2 * 32 + lane]);
                float2 v3 = __half22float2(Y[j3 * 32 + lane]);
                a0.x += v0.x; a0.y += v0.y;
                a1.x += v1.x; a1.y += v1.y;
                a2.x += v2.x; a2.y += v2.y;
                a3.x += v3.x; a3.y += v3.y;
            }
            for (; i < e; ++i) {
                float2 v = __half22float2(Y[g_col[i] * 32 + lane]);
                a0.x += v.x; a0.y += v.y;
            }
            float inv = g_invdeg[node];
            float2 z  = *(const float2*)&g_z1[node * 64 + 2 * lane];
            float hx = fmaxf((a0.x + a1.x + a2.x + a3.x) * inv + z.x, 0.f);
            float hy = fmaxf((a0.y + a1.y + a2.y + a3.y) * inv + z.y, 0.f);
            xs[nl * 68 + 2 * lane]     = hx;
            xs[nl * 68 + 2 * lane + 1] = hy;
        } else {
            xs[nl * 68 + 2 * lane]     = 0.f;
            xs[nl * 68 + 2 * lane + 1] = 0.f;
        }
    }
    __syncthreads();

    // phase 2: dual GEMM from smem
    int tx = tid & 15, ty = tid >> 4;
    int c = tx << 2, r = ty << 2;

    float4 ay[4], az[4];
    #pragma unroll
    for (int i = 0; i < 4; i++) {
        ay[i] = make_float4(0.f, 0.f, 0.f, 0.f);
        az[i] = make_float4(0.f, 0.f, 0.f, 0.f);
    }
    #pragma unroll 4
    for (int k = 0; k < 64; ++k) {
        float4 wl4 = *(const float4*)&wls[k * 64 + c];
        float4 wr4 = *(const float4*)&wrs[k * 64 + c];
        #pragma unroll
        for (int i = 0; i < 4; i++) {
            float xv = xs[(r + i) * 68 + k];
            ay[i].x += xv * wl4.x; ay[i].y += xv * wl4.y;
            ay[i].z += xv * wl4.z; ay[i].w += xv * wl4.w;
            az[i].x += xv * wr4.x; az[i].y += xv * wr4.y;
            az[i].z += xv * wr4.z; az[i].w += xv * wr4.w;
        }
    }

    float4 bb = make_float4(bs[c], bs[c + 1], bs[c + 2], bs[c + 3]);
    #pragma unroll
    for (int i = 0; i < 4; i++) {
        int g = row0 + r + i;
        if (g < n) {
            *(__half2*)&g_yb[g * 64 + c]     = __floats2half2_rn(ay[i].x, ay[i].y);
            *(__half2*)&g_yb[g * 64 + c + 2] = __floats2half2_rn(ay[i].z, ay[i].w);
            float4 zz = az[i];
            zz.x += bb.x; zz.y += bb.y; zz.z += bb.z; zz.w += bb.w;
            *(float4*)&g_z2[g * 64 + c] = zz;
        }
    }
}

// --------------------------------------------------------- final aggregate
// out[i] = inv[i]*sum yb[col] + z2[i]; also re-zeroes g_cnt for next replay.
__global__ __launch_bounds__(256) void k_agg2(float* __restrict__ O, int n) {
    int tid  = threadIdx.x;
    int lane = tid & 31, w = tid >> 5;
    int node = blockIdx.x * 8 + w;

    if (tid < 8) {
        int nn = blockIdx.x * 8 + tid;
        if (nn < n) g_cnt[nn] = 0;      // counters clean for next graph replay
    }
    if (node >= n) return;

    const __half2* Y = (const __half2*)g_yb;
    int s = g_rowptr[node], e = g_rowptr[node + 1];
    float2 a0 = {0.f,0.f}, a1 = {0.f,0.f}, a2 = {0.f,0.f}, a3 = {0.f,0.f};
    int i = s;
    for (; i + 3 < e; i += 4) {
        int j0 = g_col[i], j1 = g_col[i+1], j2 = g_col[i+2], j3 = g_col[i+3];
        float2 v0 = __half22float2(Y[j0 * 32 + lane]);
        float2 v1 = __half22float2(Y[j1 * 32 + lane]);
        float2 v2 = __half22float2(Y[j2 * 32 + lane]);
        float2 v3 = __half22float2(Y[j3 * 32 + lane]);
        a0.x += v0.x; a0.y += v0.y;
        a1.x += v1.x; a1.y += v1.y;
        a2.x += v2.x; a2.y += v2.y;
        a3.x += v3.x; a3.y += v3.y;
    }
    for (; i < e; ++i) {
        float2 v = __half22float2(Y[g_col[i] * 32 + lane]);
        a0.x += v.x; a0.y += v.y;
    }
    float inv = g_invdeg[node];
    float2 z  = *(const float2*)&g_z2[node * 64 + 2 * lane];
    float2 o;
    o.x = (a0.x + a1.x + a2.x + a3.x) * inv + z.x;
    o.y = (a0.y + a1.y + a2.y + a3.y) * inv + z.y;
    *(float2*)&O[node * 64 + 2 * lane] = o;
}

// ------------------------------------------------------------------- launch
extern "C" void kernel_launch(void* const* d_in, const int* in_sizes, int n_in,
                              void* d_out, int out_size) {
    const float* x   = (const float*)d_in[0];
    const int*   ei  = (const int*)d_in[1];
    const float* w1l = (const float*)d_in[2];
    const float* b1l = (const float*)d_in[3];
    const float* w1r = (const float*)d_in[4];
    const float* w2l = (const float*)d_in[5];
    const float* b2l = (const float*)d_in[6];
    const float* w2r = (const float*)d_in[7];
    float* out = (float*)d_out;

    int n = in_sizes[0] / F;
    int E = in_sizes[1] / 2;
    const int* src = ei;
    const int* dst = ei + E;

    int nb1024 = (n + 1023) / 1024;

    k_hist  <<<(E + 255) / 256, 256>>>(dst, E);
    k_scan1 <<<nb1024, 1024>>>(n);
    k_scan23<<<(n + 255) / 256, 256>>>(n, E, nb1024);
    k_scatter<<<(E + 255) / 256, 256>>>(src, dst, E);

    k_gemm1 <<<(n + 63) / 64, 256>>>(x, w1l, w1r, b1l, n);
    k_fused <<<(n + 63) / 64, 256>>>(w2l, w2r, b2l, n);
    k_agg2  <<<(n + 7) / 8, 256>>>(out, n);
}